// round 12
// baseline (speedup 1.0000x reference)
#include <cuda_runtime.h>
#include <cuda_fp16.h>
#include <cstdint>

#define B_ 64
#define N_ 1024
#define F_ 128
#define H_ 256

// Scratch (allocation-free rule: __device__ globals)
__device__ __half g_embs16[B_ * N_ * F_];
__device__ __half g_W016[F_ * H_];
__device__ __half g_W116[H_ * H_];
__device__ __half g_T1h[B_ * N_ * F_];
__device__ __half g_hid1h[(size_t)B_ * N_ * H_];
__device__ __half g_T2h[(size_t)B_ * N_ * H_];
__device__ __half g_hid2h[(size_t)B_ * N_ * H_];
__device__ float g_part[B_ * 8 * H_];

__device__ __forceinline__ uint32_t s2u(const void* p) {
    uint32_t a;
    asm("{ .reg .u64 t; cvta.to.shared.u64 t, %1; cvt.u32.u64 %0, t; }" : "=r"(a) : "l"(p));
    return a;
}
__device__ __forceinline__ uint32_t pack2(float a, float b) {
    __half2 h = __floats2half2_rn(a, b);   // .x = a (low), .y = b
    return *(uint32_t*)&h;
}
__device__ __forceinline__ void ldsm4(uint32_t* r, uint32_t addr) {
    asm volatile("ldmatrix.sync.aligned.m8n8.x4.shared.b16 {%0,%1,%2,%3}, [%4];"
                 : "=r"(r[0]), "=r"(r[1]), "=r"(r[2]), "=r"(r[3]) : "r"(addr));
}
__device__ __forceinline__ void ldsm4t(uint32_t* r, uint32_t addr) {
    asm volatile("ldmatrix.sync.aligned.m8n8.x4.trans.shared.b16 {%0,%1,%2,%3}, [%4];"
                 : "=r"(r[0]), "=r"(r[1]), "=r"(r[2]), "=r"(r[3]) : "r"(addr));
}
__device__ __forceinline__ void mma_h(float* d, const uint32_t* a, const uint32_t* b) {
    asm volatile(
        "mma.sync.aligned.m16n8k16.row.col.f32.f16.f16.f32 "
        "{%0,%1,%2,%3}, {%4,%5,%6,%7}, {%8,%9}, {%0,%1,%2,%3};"
        : "+f"(d[0]), "+f"(d[1]), "+f"(d[2]), "+f"(d[3])
        : "r"(a[0]), "r"(a[1]), "r"(a[2]), "r"(a[3]), "r"(b[0]), "r"(b[1]));
}
__device__ __forceinline__ void cpasync16(uint32_t dst, const void* src) {
    asm volatile("cp.async.cg.shared.global [%0], [%1], 16;" :: "r"(dst), "l"(src));
}
__device__ __forceinline__ void cp_commit() { asm volatile("cp.async.commit_group;"); }

// ---------------------------------------------------------------------------
// fp16 GEMM: C[M,N](half) = A[M,K] @ B[K,N](half), f32 accumulate.
// CTA tile 128x128x64, 128 thr, 2x2 warps, warp 64x64, mma m16n8k16.
// A smem: 128 rows x 64 half (128B rows), f4-XOR swizzle.
//   ADJ_A=0: A is half, cp.async 3-stage.
//   ADJ_A=1: A is fp32 (adj); one thread per row: 16x LDG.128 ->
//            cvt.rne -> 8x swizzled STS.128, reg-staged 2-stage.
// B smem: 64 k-rows x 128 n half (256B rows), swizzle
//   byte = k*256 + (nseg>>3)*128 + (((nseg&7)^(k&7))<<4); consumed with
//   ldmatrix.x4.trans straight from k-major storage.
// Frag double-buffering across the 4 k16 sections per tile.
// Epilogue: bias+relu on f32 acc, pack to half2, store C as fp16.
// SMEM: A stages at 0 (16KB ea, 3 slots), B stages at 49152 (16KB ea x2).
// ---------------------------------------------------------------------------
template <int ADJ_A>
__global__ __launch_bounds__(128)
void gemm_h(const void* Avoid, const __half* __restrict__ Bg,
            __half* __restrict__ Cg, int K, int nk, int ldb,
            long sA, long sB, long sC, const float* __restrict__ bias, int relu)
{
    extern __shared__ float smp[];
    const uint32_t smb = s2u(smp);
    const int tid = threadIdx.x;
    const int lid = tid & 31;
    const int wid = tid >> 5;
    const int mw = wid >> 1;
    const int nw = wid & 1;

    const float*  Af = (const float*)Avoid + blockIdx.z * sA + (size_t)blockIdx.y * 128 * K;
    const __half* Ah = (const __half*)Avoid + blockIdx.z * sA + (size_t)blockIdx.y * 128 * K;
    const __half* Bh = Bg + blockIdx.z * sB + blockIdx.x * 128;
    __half* C = Cg + blockIdx.z * sC + (size_t)blockIdx.y * 128 * ldb + blockIdx.x * 128;
    if (bias) bias += blockIdx.x * 128;

    // ---- A producer, fp16 source: 8x cp.async(16B) per stage ----
    auto issueA = [&](int kt, int st) {
        const uint32_t dstb = smb + st * 16384;
        const __half* src = Ah + (size_t)kt * 64 + (tid & 7) * 8;
#pragma unroll
        for (int j = 0; j < 8; j++) {
            int row = (tid >> 3) + j * 16;
            cpasync16(dstb + row * 128 + (((tid & 7) ^ (row & 7)) << 4),
                      src + (size_t)row * K);
        }
        cp_commit();
    };

    // ---- A producer, adj fp32: thread = row; 16 LDG.128 -> cvt -> 8 STS.128 ----
    uint4 hv[8];
    auto ldgA = [&](int kt) {
        const float* src = Af + (size_t)tid * K + kt * 64;
#pragma unroll
        for (int jj = 0; jj < 8; jj++) {
            float4 u = *(const float4*)(src + jj * 8);
            float4 v = *(const float4*)(src + jj * 8 + 4);
            hv[jj].x = pack2(u.x, u.y);
            hv[jj].y = pack2(u.z, u.w);
            hv[jj].z = pack2(v.x, v.y);
            hv[jj].w = pack2(v.z, v.w);
        }
    };
    auto stsA = [&](int st) {
        char* base = (char*)smp + st * 16384 + tid * 128;
#pragma unroll
        for (int jj = 0; jj < 8; jj++)
            *(uint4*)(base + ((jj ^ (tid & 7)) << 4)) = hv[jj];
    };

    // ---- B producer: 8x cp.async(16B) per stage ----
    auto issueB = [&](int kt, int st) {
        const uint32_t dstb = smb + 49152 + st * 16384;
#pragma unroll
        for (int j = 0; j < 8; j++) {
            int s = tid + j * 128;
            int k = s >> 4, nseg = s & 15;
            cpasync16(dstb + k * 256 + (nseg >> 3) * 128 + (((nseg & 7) ^ (k & 7)) << 4),
                      Bh + (size_t)(kt * 64 + k) * ldb + nseg * 8);
        }
        cp_commit();
    };

    // ---- per-lane ldmatrix bases ----
    int aR128[4], aR7[4];
    const int l4a = (lid >> 4) & 1;
#pragma unroll
    for (int mf = 0; mf < 4; mf++) {
        int r = mw * 64 + mf * 16 + (lid & 7) + 8 * ((lid >> 3) & 1);
        aR128[mf] = r * 128;
        aR7[mf] = r & 7;
    }
    const int t3 = (lid >> 3) & 1;
    const int kkterm = ((lid & 7) + 8 * ((lid >> 4) & 1)) * 256;
    int bOff[4];
#pragma unroll
    for (int p = 0; p < 4; p++)
        bOff[p] = nw * 128 + (((p * 2 + t3) ^ (lid & 7)) << 4);

    float acc[4][8][4];
#pragma unroll
    for (int mf = 0; mf < 4; mf++)
#pragma unroll
        for (int nf = 0; nf < 8; nf++)
#pragma unroll
            for (int e = 0; e < 4; e++) acc[mf][nf][e] = 0.f;

    // ---- prologue (nk >= 2 always) ----
    if (ADJ_A) {
        ldgA(0);
        issueB(0, 0);
        stsA(0);
        ldgA(1);
        asm volatile("cp.async.wait_group 0;");
    } else {
        issueB(0, 0);
        issueA(0, 0);
        issueA(1, 1);
        asm volatile("cp.async.wait_group 1;");
    }
    __syncthreads();

    int sa = 0;
    for (int t = 0; t < nk; t++) {
        if (ADJ_A) {
            if (t + 1 < nk) { stsA((t + 1) & 1); issueB(t + 1, (t + 1) & 1); }
            if (t + 2 < nk) ldgA(t + 2);
        } else {
            if (t + 1 < nk) issueB(t + 1, (t + 1) & 1);
            if (t + 2 < nk) issueA(t + 2, (t + 2) % 3);
        }

        const uint32_t Ab = smb + (ADJ_A ? ((t & 1) * 16384) : (sa * 16384));
        const uint32_t Bb = smb + 49152 + (t & 1) * 16384;

        uint32_t a[2][4][4], b[2][8][2];
        auto ldfr = [&](int kb, int pb) {
#pragma unroll
            for (int mf = 0; mf < 4; mf++)
                ldsm4(a[pb][mf], Ab + aR128[mf] + ((((kb << 1) | l4a) ^ aR7[mf]) << 4));
#pragma unroll
            for (int p = 0; p < 4; p++) {
                uint32_t r[4];
                ldsm4t(r, Bb + kb * 4096 + kkterm + bOff[p]);
                b[pb][2 * p][0] = r[0];     b[pb][2 * p][1] = r[2];
                b[pb][2 * p + 1][0] = r[1]; b[pb][2 * p + 1][1] = r[3];
            }
        };

        ldfr(0, 0);
#pragma unroll
        for (int kb = 0; kb < 4; kb++) {
            if (kb < 3) ldfr(kb + 1, (kb + 1) & 1);
            const int pb = kb & 1;
#pragma unroll
            for (int mf = 0; mf < 4; mf++)
#pragma unroll
                for (int nf = 0; nf < 8; nf++)
                    mma_h(acc[mf][nf], a[pb][mf], b[pb][nf]);
        }

        if (t + 1 < nk) {
            if (!ADJ_A && t + 2 < nk) asm volatile("cp.async.wait_group 1;");
            else                      asm volatile("cp.async.wait_group 0;");
        }
        __syncthreads();
        sa = (sa + 1 == 3) ? 0 : sa + 1;
    }

    // ---- epilogue: bias + relu on f32, pack to half2 ----
    const int r0 = mw * 64 + (lid >> 2);
    const int c0 = nw * 64 + (lid & 3) * 2;
#pragma unroll
    for (int mf = 0; mf < 4; mf++) {
        const int row = r0 + mf * 16;
#pragma unroll
        for (int nf = 0; nf < 8; nf++) {
            const int col = c0 + nf * 8;
            float2 v0 = make_float2(acc[mf][nf][0], acc[mf][nf][1]);
            float2 v1 = make_float2(acc[mf][nf][2], acc[mf][nf][3]);
            if (bias) {
                float bx = bias[col], by = bias[col + 1];
                v0.x += bx; v0.y += by; v1.x += bx; v1.y += by;
            }
            if (relu) {
                v0.x = fmaxf(v0.x, 0.f); v0.y = fmaxf(v0.y, 0.f);
                v1.x = fmaxf(v1.x, 0.f); v1.y = fmaxf(v1.y, 0.f);
            }
            *(uint32_t*)(C + (size_t)row * ldb + col) = pack2(v0.x, v0.y);
            *(uint32_t*)(C + (size_t)(row + 8) * ldb + col) = pack2(v1.x, v1.y);
        }
    }
}

// ---------------- prep: fp32 -> fp16 elementwise (count % 4 == 0) ----------
__global__ __launch_bounds__(256)
void cvt_kernel(const float4* __restrict__ in, uint2* __restrict__ out, int n4)
{
    int i = blockIdx.x * 256 + threadIdx.x;
    if (i < n4) {
        float4 v = in[i];
        uint2 o;
        o.x = pack2(v.x, v.y);
        o.y = pack2(v.z, v.w);
        out[i] = o;
    }
}

// ---------------- tail1: partial dot over a 128-node slice -----------------
__global__ __launch_bounds__(256)
void tail1_kernel(const float* __restrict__ adj, const __half* __restrict__ hid2,
                  float* __restrict__ part)
{
    const int s = blockIdx.x;
    const int b = blockIdx.y;
    const int h = threadIdx.x;
    __shared__ float arow[128];

    const float* ar = adj + (size_t)b * N_ * N_ + s * 128;
    if (h < 128) arow[h] = ar[h];
    __syncthreads();

    const __half* h2 = hid2 + (size_t)b * N_ * H_ + (size_t)s * 128 * H_ + h;
    float acc = 0.f;
#pragma unroll 8
    for (int n = 0; n < 128; n++)
        acc = fmaf(arow[n], __half2float(h2[(size_t)n * H_]), acc);
    part[(b * 8 + s) * H_ + h] = acc;
}

// ---------------- tail2: reduce + W2(relu) + Wl head -----------------------
__global__ __launch_bounds__(256)
void tail2_kernel(const float* __restrict__ part,
                  const float* __restrict__ W2, const float* __restrict__ b2,
                  const float* __restrict__ Wl, const float* __restrict__ bl,
                  float* __restrict__ out)
{
    const int b = blockIdx.x;
    const int t = threadIdx.x;
    __shared__ float rs[H_];
    __shared__ float ss[H_];

    {
        const float* p = part + b * 8 * H_ + t;
        float a = p[0];
#pragma unroll
        for (int s = 1; s < 8; s++) a += p[s * H_];
        rs[t] = a;
    }
    __syncthreads();

    {
        float a2 = b2[t];
#pragma unroll 8
        for (int k = 0; k < H_; k++)
            a2 = fmaf(rs[k], W2[k * H_ + t], a2);
        ss[t] = fmaxf(a2, 0.f);
    }
    __syncthreads();

    if (t < F_) {
        float a3 = bl[t];
#pragma unroll 8
        for (int k = 0; k < H_; k++)
            a3 = fmaf(ss[k], Wl[k * F_ + t], a3);
        out[b * F_ + t] = a3;
    }
}

// ---------------- launch ----------------
template <int ADJ_A>
static void launch_gemm(const void* A, const __half* Bm, __half* C,
                        int gridN, int gridM, int batch, int K, int ldb,
                        long sA, long sB, long sC, const float* bias, int relu)
{
    const int smem = 81920;
    cudaFuncSetAttribute(gemm_h<ADJ_A>,
                         cudaFuncAttributeMaxDynamicSharedMemorySize, smem);
    gemm_h<ADJ_A><<<dim3(gridN, gridM, batch), 128, smem>>>(
        A, Bm, C, K, K / 64, ldb, sA, sB, sC, bias, relu);
}

extern "C" void kernel_launch(void* const* d_in, const int* in_sizes, int n_in,
                              void* d_out, int out_size)
{
    const float* embs = (const float*)d_in[0];
    const float* adj  = (const float*)d_in[1];
    const float* W0   = (const float*)d_in[2];
    const float* b0   = (const float*)d_in[3];
    const float* W1   = (const float*)d_in[4];
    const float* b1   = (const float*)d_in[5];
    const float* W2   = (const float*)d_in[6];
    const float* b2   = (const float*)d_in[7];
    const float* Wl   = (const float*)d_in[8];
    const float* bl   = (const float*)d_in[9];
    float* out = (float*)d_out;

    __half *embs16, *W016, *W116, *T1h, *hid1h, *T2h, *hid2h;
    float* part;
    cudaGetSymbolAddress((void**)&embs16, g_embs16);
    cudaGetSymbolAddress((void**)&W016, g_W016);
    cudaGetSymbolAddress((void**)&W116, g_W116);
    cudaGetSymbolAddress((void**)&T1h, g_T1h);
    cudaGetSymbolAddress((void**)&hid1h, g_hid1h);
    cudaGetSymbolAddress((void**)&T2h, g_T2h);
    cudaGetSymbolAddress((void**)&hid2h, g_hid2h);
    cudaGetSymbolAddress((void**)&part, g_part);

    // prep: convert B-side fp32 inputs to fp16
    {
        int n4e = B_ * N_ * F_ / 4;
        cvt_kernel<<<(n4e + 255) / 256, 256>>>((const float4*)embs, (uint2*)embs16, n4e);
        int n40 = F_ * H_ / 4;
        cvt_kernel<<<(n40 + 255) / 256, 256>>>((const float4*)W0, (uint2*)W016, n40);
        int n41 = H_ * H_ / 4;
        cvt_kernel<<<(n41 + 255) / 256, 256>>>((const float4*)W1, (uint2*)W116, n41);
    }

    // L0A: T1 = adj @ embs            per graph [1024x1024]@[1024x128]
    launch_gemm<1>(adj, embs16, T1h, 1, 8, B_, N_, F_,
                   (long)N_ * N_, (long)N_ * F_, (long)N_ * F_, nullptr, 0);
    // L0B: hid1 = relu(T1 @ W0 + b0)  [65536x128]@[128x256]
    launch_gemm<0>(T1h, W016, hid1h, 2, 512, 1, F_, H_, 0, 0, 0, b0, 1);
    // L1A: T2 = hid1 @ W1             [65536x256]@[256x256]
    launch_gemm<0>(hid1h, W116, T2h, 2, 512, 1, H_, H_, 0, 0, 0, nullptr, 0);
    // L1B: hid2 = relu(adj @ T2 + b1) per graph [1024x1024]@[1024x256]
    launch_gemm<1>(adj, T2h, hid2h, 2, 8, B_, N_, H_,
                   (long)N_ * N_, (long)N_ * H_, (long)N_ * H_, b1, 1);
    // tail: L2 (node-0 slice) + linear head
    tail1_kernel<<<dim3(8, B_), 256>>>(adj, hid2h, part);
    tail2_kernel<<<B_, 256>>>(part, W2, b2, Wl, bl, out);
}

// round 13
// speedup vs baseline: 1.3469x; 1.3469x over previous
#include <cuda_runtime.h>
#include <cuda_fp16.h>
#include <cstdint>

#define B_ 64
#define N_ 1024
#define F_ 128
#define H_ 256

// Scratch (allocation-free rule: __device__ globals)
__device__ __half g_adj16[(size_t)B_ * N_ * N_];   // adj, fp16 (rne), 134MB
__device__ __half g_embs16[B_ * N_ * F_];
__device__ __half g_W016[F_ * H_];
__device__ __half g_W116[H_ * H_];
__device__ __half g_T1h[B_ * N_ * F_];
__device__ __half g_hid1h[(size_t)B_ * N_ * H_];
__device__ __half g_T2h[(size_t)B_ * N_ * H_];
__device__ __half g_hid2h[(size_t)B_ * N_ * H_];
__device__ float g_part[B_ * 8 * H_];

__device__ __forceinline__ uint32_t s2u(const void* p) {
    uint32_t a;
    asm("{ .reg .u64 t; cvta.to.shared.u64 t, %1; cvt.u32.u64 %0, t; }" : "=r"(a) : "l"(p));
    return a;
}
__device__ __forceinline__ uint32_t pack2(float a, float b) {
    __half2 h = __floats2half2_rn(a, b);   // .x = a (low), .y = b
    return *(uint32_t*)&h;
}
__device__ __forceinline__ void ldsm4(uint32_t* r, uint32_t addr) {
    asm volatile("ldmatrix.sync.aligned.m8n8.x4.shared.b16 {%0,%1,%2,%3}, [%4];"
                 : "=r"(r[0]), "=r"(r[1]), "=r"(r[2]), "=r"(r[3]) : "r"(addr));
}
__device__ __forceinline__ void ldsm4t(uint32_t* r, uint32_t addr) {
    asm volatile("ldmatrix.sync.aligned.m8n8.x4.trans.shared.b16 {%0,%1,%2,%3}, [%4];"
                 : "=r"(r[0]), "=r"(r[1]), "=r"(r[2]), "=r"(r[3]) : "r"(addr));
}
__device__ __forceinline__ void mma_h(float* d, const uint32_t* a, const uint32_t* b) {
    asm volatile(
        "mma.sync.aligned.m16n8k16.row.col.f32.f16.f16.f32 "
        "{%0,%1,%2,%3}, {%4,%5,%6,%7}, {%8,%9}, {%0,%1,%2,%3};"
        : "+f"(d[0]), "+f"(d[1]), "+f"(d[2]), "+f"(d[3])
        : "r"(a[0]), "r"(a[1]), "r"(a[2]), "r"(a[3]), "r"(b[0]), "r"(b[1]));
}
__device__ __forceinline__ void cpasync16(uint32_t dst, const void* src) {
    asm volatile("cp.async.cg.shared.global [%0], [%1], 16;" :: "r"(dst), "l"(src));
}
__device__ __forceinline__ void cp_commit() { asm volatile("cp.async.commit_group;"); }

// ---------------------------------------------------------------------------
// Unified fp16 GEMM: C[M,N](half) = A[M,K](half) @ B[K,N](half), f32 acc.
// CTA tile 128x128x64, 128 thr, 2x2 warps, warp 64x64, mma m16n8k16.
// Both operands cp.async, 3 stages each, ONE commit group per k-tile,
// lookahead 2, wait_group 1 -> deep fire-and-forget load pipeline.
// A smem: 128 rows x 128B (64 half), f4-XOR swizzle.
// B smem: 64 k-rows x 256B (128 half n), swizzle
//   byte = k*256 + (nseg>>3)*128 + (((nseg&7)^(k&7))<<4); consumed via
//   ldmatrix.x4.trans straight from k-major storage.
// Frag double-buffering across the 4 k16 sections per tile.
// Epilogue: bias+relu on f32 acc, pack to half2, store C fp16.
// SMEM: A stages [0,48K), B stages [48K,96K).
// ---------------------------------------------------------------------------
__global__ __launch_bounds__(128)
void gemm_h(const __half* __restrict__ Ag, const __half* __restrict__ Bg,
            __half* __restrict__ Cg, int K, int nk, int ldb,
            long sA, long sB, long sC, const float* __restrict__ bias, int relu)
{
    extern __shared__ float smp[];
    const uint32_t smb = s2u(smp);
    const int tid = threadIdx.x;
    const int lid = tid & 31;
    const int wid = tid >> 5;
    const int mw = wid >> 1;
    const int nw = wid & 1;

    const __half* Ah = Ag + blockIdx.z * sA + (size_t)blockIdx.y * 128 * K;
    const __half* Bh = Bg + blockIdx.z * sB + blockIdx.x * 128;
    __half* C = Cg + blockIdx.z * sC + (size_t)blockIdx.y * 128 * ldb + blockIdx.x * 128;
    if (bias) bias += blockIdx.x * 128;

    // ---- A producer: 8x cp.async(16B) ----
    auto issueA = [&](int kt, int st) {
        const uint32_t dstb = smb + st * 16384;
        const __half* src = Ah + (size_t)kt * 64 + (tid & 7) * 8;
#pragma unroll
        for (int j = 0; j < 8; j++) {
            int row = (tid >> 3) + j * 16;
            cpasync16(dstb + row * 128 + (((tid & 7) ^ (row & 7)) << 4),
                      src + (size_t)row * K);
        }
    };

    // ---- B producer: 8x cp.async(16B) ----
    auto issueB = [&](int kt, int st) {
        const uint32_t dstb = smb + 49152 + st * 16384;
#pragma unroll
        for (int j = 0; j < 8; j++) {
            int s = tid + j * 128;
            int k = s >> 4, nseg = s & 15;
            cpasync16(dstb + k * 256 + (nseg >> 3) * 128 + (((nseg & 7) ^ (k & 7)) << 4),
                      Bh + (size_t)(kt * 64 + k) * ldb + nseg * 8);
        }
    };

    // ---- per-lane ldmatrix bases ----
    int aR128[4], aR7[4];
    const int l4a = (lid >> 4) & 1;
#pragma unroll
    for (int mf = 0; mf < 4; mf++) {
        int r = mw * 64 + mf * 16 + (lid & 7) + 8 * ((lid >> 3) & 1);
        aR128[mf] = r * 128;
        aR7[mf] = r & 7;
    }
    const int t3 = (lid >> 3) & 1;
    const int kkterm = ((lid & 7) + 8 * ((lid >> 4) & 1)) * 256;
    int bOff[4];
#pragma unroll
    for (int p = 0; p < 4; p++)
        bOff[p] = nw * 128 + (((p * 2 + t3) ^ (lid & 7)) << 4);

    float acc[4][8][4];
#pragma unroll
    for (int mf = 0; mf < 4; mf++)
#pragma unroll
        for (int nf = 0; nf < 8; nf++)
#pragma unroll
            for (int e = 0; e < 4; e++) acc[mf][nf][e] = 0.f;

    // ---- prologue (nk >= 2 always) ----
    issueA(0, 0); issueB(0, 0); cp_commit();
    issueA(1, 1); issueB(1, 1); cp_commit();
    asm volatile("cp.async.wait_group 1;");
    __syncthreads();

    for (int t = 0; t < nk; t++) {
        if (t + 2 < nk) {
            // stage (t+2)%3 == (t-1)%3: freed by the sync at end of iter t-1
            issueA(t + 2, (t + 2) % 3);
            issueB(t + 2, (t + 2) % 3);
            cp_commit();
        }

        const uint32_t Ab = smb + (t % 3) * 16384;
        const uint32_t Bb = smb + 49152 + (t % 3) * 16384;

        uint32_t a[2][4][4], b[2][8][2];
        auto ldfr = [&](int kb, int pb) {
#pragma unroll
            for (int mf = 0; mf < 4; mf++)
                ldsm4(a[pb][mf], Ab + aR128[mf] + ((((kb << 1) | l4a) ^ aR7[mf]) << 4));
#pragma unroll
            for (int p = 0; p < 4; p++) {
                uint32_t r[4];
                ldsm4t(r, Bb + kb * 4096 + kkterm + bOff[p]);
                b[pb][2 * p][0] = r[0];     b[pb][2 * p][1] = r[2];
                b[pb][2 * p + 1][0] = r[1]; b[pb][2 * p + 1][1] = r[3];
            }
        };

        ldfr(0, 0);
#pragma unroll
        for (int kb = 0; kb < 4; kb++) {
            if (kb < 3) ldfr(kb + 1, (kb + 1) & 1);
            const int pb = kb & 1;
#pragma unroll
            for (int mf = 0; mf < 4; mf++)
#pragma unroll
                for (int nf = 0; nf < 8; nf++)
                    mma_h(acc[mf][nf], a[pb][mf], b[pb][nf]);
        }

        if (t + 1 < nk) {
            if (t + 2 < nk) asm volatile("cp.async.wait_group 1;");
            else            asm volatile("cp.async.wait_group 0;");
            __syncthreads();
        }
    }

    // ---- epilogue: bias + relu on f32, pack to half2 ----
    const int r0 = mw * 64 + (lid >> 2);
    const int c0 = nw * 64 + (lid & 3) * 2;
#pragma unroll
    for (int mf = 0; mf < 4; mf++) {
        const int row = r0 + mf * 16;
#pragma unroll
        for (int nf = 0; nf < 8; nf++) {
            const int col = c0 + nf * 8;
            float2 v0 = make_float2(acc[mf][nf][0], acc[mf][nf][1]);
            float2 v1 = make_float2(acc[mf][nf][2], acc[mf][nf][3]);
            if (bias) {
                float bx = bias[col], by = bias[col + 1];
                v0.x += bx; v0.y += by; v1.x += bx; v1.y += by;
            }
            if (relu) {
                v0.x = fmaxf(v0.x, 0.f); v0.y = fmaxf(v0.y, 0.f);
                v1.x = fmaxf(v1.x, 0.f); v1.y = fmaxf(v1.y, 0.f);
            }
            *(uint32_t*)(C + (size_t)row * ldb + col) = pack2(v0.x, v0.y);
            *(uint32_t*)(C + (size_t)(row + 8) * ldb + col) = pack2(v1.x, v1.y);
        }
    }
}

// ---------------- prep: fp32 -> fp16 streaming (grid-stride) ---------------
__global__ __launch_bounds__(256)
void cvt_kernel(const float4* __restrict__ in, uint2* __restrict__ out, int n4)
{
    int stride = gridDim.x * 256;
    for (int i = blockIdx.x * 256 + threadIdx.x; i < n4; i += stride) {
        float4 v = in[i];
        uint2 o;
        o.x = pack2(v.x, v.y);
        o.y = pack2(v.z, v.w);
        out[i] = o;
    }
}

// ---------------- tail1: partial dot over a 128-node slice -----------------
__global__ __launch_bounds__(256)
void tail1_kernel(const float* __restrict__ adj, const __half* __restrict__ hid2,
                  float* __restrict__ part)
{
    const int s = blockIdx.x;
    const int b = blockIdx.y;
    const int h = threadIdx.x;
    __shared__ float arow[128];

    const float* ar = adj + (size_t)b * N_ * N_ + s * 128;
    if (h < 128) arow[h] = ar[h];
    __syncthreads();

    const __half* h2 = hid2 + (size_t)b * N_ * H_ + (size_t)s * 128 * H_ + h;
    float acc = 0.f;
#pragma unroll 8
    for (int n = 0; n < 128; n++)
        acc = fmaf(arow[n], __half2float(h2[(size_t)n * H_]), acc);
    part[(b * 8 + s) * H_ + h] = acc;
}

// ---------------- tail2: reduce + W2(relu) + Wl head -----------------------
__global__ __launch_bounds__(256)
void tail2_kernel(const float* __restrict__ part,
                  const float* __restrict__ W2, const float* __restrict__ b2,
                  const float* __restrict__ Wl, const float* __restrict__ bl,
                  float* __restrict__ out)
{
    const int b = blockIdx.x;
    const int t = threadIdx.x;
    __shared__ float rs[H_];
    __shared__ float ss[H_];

    {
        const float* p = part + b * 8 * H_ + t;
        float a = p[0];
#pragma unroll
        for (int s = 1; s < 8; s++) a += p[s * H_];
        rs[t] = a;
    }
    __syncthreads();

    {
        float a2 = b2[t];
#pragma unroll 8
        for (int k = 0; k < H_; k++)
            a2 = fmaf(rs[k], W2[k * H_ + t], a2);
        ss[t] = fmaxf(a2, 0.f);
    }
    __syncthreads();

    if (t < F_) {
        float a3 = bl[t];
#pragma unroll 8
        for (int k = 0; k < H_; k++)
            a3 = fmaf(ss[k], Wl[k * F_ + t], a3);
        out[b * F_ + t] = a3;
    }
}

// ---------------- launch ----------------
static void launch_gemm(const __half* A, const __half* Bm, __half* C,
                        int gridN, int gridM, int batch, int K, int ldb,
                        long sA, long sB, long sC, const float* bias, int relu)
{
    const int smem = 98304;  // 3x16KB A + 3x16KB B
    cudaFuncSetAttribute(gemm_h, cudaFuncAttributeMaxDynamicSharedMemorySize, smem);
    gemm_h<<<dim3(gridN, gridM, batch), 128, smem>>>(
        A, Bm, C, K, K / 64, ldb, sA, sB, sC, bias, relu);
}

extern "C" void kernel_launch(void* const* d_in, const int* in_sizes, int n_in,
                              void* d_out, int out_size)
{
    const float* embs = (const float*)d_in[0];
    const float* adj  = (const float*)d_in[1];
    const float* W0   = (const float*)d_in[2];
    const float* b0   = (const float*)d_in[3];
    const float* W1   = (const float*)d_in[4];
    const float* b1   = (const float*)d_in[5];
    const float* W2   = (const float*)d_in[6];
    const float* b2   = (const float*)d_in[7];
    const float* Wl   = (const float*)d_in[8];
    const float* bl   = (const float*)d_in[9];
    float* out = (float*)d_out;

    __half *adj16, *embs16, *W016, *W116, *T1h, *hid1h, *T2h, *hid2h;
    float* part;
    cudaGetSymbolAddress((void**)&adj16, g_adj16);
    cudaGetSymbolAddress((void**)&embs16, g_embs16);
    cudaGetSymbolAddress((void**)&W016, g_W016);
    cudaGetSymbolAddress((void**)&W116, g_W116);
    cudaGetSymbolAddress((void**)&T1h, g_T1h);
    cudaGetSymbolAddress((void**)&hid1h, g_hid1h);
    cudaGetSymbolAddress((void**)&T2h, g_T2h);
    cudaGetSymbolAddress((void**)&hid2h, g_hid2h);
    cudaGetSymbolAddress((void**)&part, g_part);

    // prep: convert fp32 inputs to fp16 (rne) — adj is the big one (268MB)
    {
        int n4a = (int)((size_t)B_ * N_ * N_ / 4);
        cvt_kernel<<<2048, 256>>>((const float4*)adj, (uint2*)adj16, n4a);
        int n4e = B_ * N_ * F_ / 4;
        cvt_kernel<<<512, 256>>>((const float4*)embs, (uint2*)embs16, n4e);
        int n40 = F_ * H_ / 4;
        cvt_kernel<<<32, 256>>>((const float4*)W0, (uint2*)W016, n40);
        int n41 = H_ * H_ / 4;
        cvt_kernel<<<64, 256>>>((const float4*)W1, (uint2*)W116, n41);
    }

    // L0A: T1 = adj @ embs            per graph [1024x1024]@[1024x128]
    launch_gemm(adj16, embs16, T1h, 1, 8, B_, N_, F_,
                (long)N_ * N_, (long)N_ * F_, (long)N_ * F_, nullptr, 0);
    // L0B: hid1 = relu(T1 @ W0 + b0)  [65536x128]@[128x256]
    launch_gemm(T1h, W016, hid1h, 2, 512, 1, F_, H_, 0, 0, 0, b0, 1);
    // L1A: T2 = hid1 @ W1             [65536x256]@[256x256]
    launch_gemm(hid1h, W116, T2h, 2, 512, 1, H_, H_, 0, 0, 0, nullptr, 0);
    // L1B: hid2 = relu(adj @ T2 + b1) per graph [1024x1024]@[1024x256]
    launch_gemm(adj16, T2h, hid2h, 2, 8, B_, N_, H_,
                (long)N_ * N_, (long)N_ * H_, (long)N_ * H_, b1, 1);
    // tail: L2 (node-0 slice) + linear head
    tail1_kernel<<<dim3(8, B_), 256>>>(adj, hid2h, part);
    tail2_kernel<<<B_, 256>>>(part, W2, b2, Wl, bl, out);
}

// round 14
// speedup vs baseline: 1.4147x; 1.0504x over previous
#include <cuda_runtime.h>
#include <cuda_fp16.h>
#include <cstdint>

#define B_ 64
#define N_ 1024
#define F_ 128
#define H_ 256

// Scratch (allocation-free rule: __device__ globals)
__device__ __half g_adj16[(size_t)B_ * N_ * N_];   // adj, fp16 (rne)
__device__ __half g_embs16[B_ * N_ * F_];
__device__ __half g_W016[F_ * H_];
__device__ __half g_W116[H_ * H_];
__device__ __half g_T1h[B_ * N_ * F_];
__device__ __half g_hid1h[(size_t)B_ * N_ * H_];
__device__ __half g_T2h[(size_t)B_ * N_ * H_];
__device__ float g_part[B_ * 8 * H_];              // [b][ytile][col]

__device__ __forceinline__ uint32_t s2u(const void* p) {
    uint32_t a;
    asm("{ .reg .u64 t; cvta.to.shared.u64 t, %1; cvt.u32.u64 %0, t; }" : "=r"(a) : "l"(p));
    return a;
}
__device__ __forceinline__ uint32_t pack2(float a, float b) {
    __half2 h = __floats2half2_rn(a, b);
    return *(uint32_t*)&h;
}
__device__ __forceinline__ void ldsm4(uint32_t* r, uint32_t addr) {
    asm volatile("ldmatrix.sync.aligned.m8n8.x4.shared.b16 {%0,%1,%2,%3}, [%4];"
                 : "=r"(r[0]), "=r"(r[1]), "=r"(r[2]), "=r"(r[3]) : "r"(addr));
}
__device__ __forceinline__ void ldsm4t(uint32_t* r, uint32_t addr) {
    asm volatile("ldmatrix.sync.aligned.m8n8.x4.trans.shared.b16 {%0,%1,%2,%3}, [%4];"
                 : "=r"(r[0]), "=r"(r[1]), "=r"(r[2]), "=r"(r[3]) : "r"(addr));
}
__device__ __forceinline__ void mma_h(float* d, const uint32_t* a, const uint32_t* b) {
    asm volatile(
        "mma.sync.aligned.m16n8k16.row.col.f32.f16.f16.f32 "
        "{%0,%1,%2,%3}, {%4,%5,%6,%7}, {%8,%9}, {%0,%1,%2,%3};"
        : "+f"(d[0]), "+f"(d[1]), "+f"(d[2]), "+f"(d[3])
        : "r"(a[0]), "r"(a[1]), "r"(a[2]), "r"(a[3]), "r"(b[0]), "r"(b[1]));
}
__device__ __forceinline__ void cpasync16(uint32_t dst, const void* src) {
    asm volatile("cp.async.cg.shared.global [%0], [%1], 16;" :: "r"(dst), "l"(src));
}
__device__ __forceinline__ void cp_commit() { asm volatile("cp.async.commit_group;"); }

// ---------------------------------------------------------------------------
// Unified fp16 GEMM (R13 mainloop, unchanged): C = A @ B, f32 acc.
// CTA 128x128x64, 128 thr, 2x2 warps, warp 64x64, 3-stage dual cp.async.
// FUSE_TAIL=0: epilogue bias+relu -> C (fp16).
// FUSE_TAIL=1 (L1B): epilogue computes hid2 = relu(acc + b1) in registers,
//   weights by adjw[b,0,row] (fp32), reduces over the CTA's 128 rows
//   (shfl over lanes sharing columns, smem over the 2 m-warps), and writes
//   part[b][blockIdx.y][blockIdx.x*128 + col]. No C store; hid2 never hits DRAM.
// ---------------------------------------------------------------------------
template <int FUSE_TAIL>
__global__ __launch_bounds__(128)
void gemm_h(const __half* __restrict__ Ag, const __half* __restrict__ Bg,
            __half* __restrict__ Cg, int K, int nk, int ldb,
            long sA, long sB, long sC, const float* __restrict__ bias, int relu,
            const float* __restrict__ adjw, float* __restrict__ part)
{
    extern __shared__ float smp[];
    const uint32_t smb = s2u(smp);
    const int tid = threadIdx.x;
    const int lid = tid & 31;
    const int wid = tid >> 5;
    const int mw = wid >> 1;
    const int nw = wid & 1;

    const __half* Ah = Ag + blockIdx.z * sA + (size_t)blockIdx.y * 128 * K;
    const __half* Bh = Bg + blockIdx.z * sB + blockIdx.x * 128;
    __half* C = Cg + blockIdx.z * sC + (size_t)blockIdx.y * 128 * ldb + blockIdx.x * 128;
    if (bias) bias += blockIdx.x * 128;

    auto issueA = [&](int kt, int st) {
        const uint32_t dstb = smb + st * 16384;
        const __half* src = Ah + (size_t)kt * 64 + (tid & 7) * 8;
#pragma unroll
        for (int j = 0; j < 8; j++) {
            int row = (tid >> 3) + j * 16;
            cpasync16(dstb + row * 128 + (((tid & 7) ^ (row & 7)) << 4),
                      src + (size_t)row * K);
        }
    };
    auto issueB = [&](int kt, int st) {
        const uint32_t dstb = smb + 49152 + st * 16384;
#pragma unroll
        for (int j = 0; j < 8; j++) {
            int s = tid + j * 128;
            int k = s >> 4, nseg = s & 15;
            cpasync16(dstb + k * 256 + (nseg >> 3) * 128 + (((nseg & 7) ^ (k & 7)) << 4),
                      Bh + (size_t)(kt * 64 + k) * ldb + nseg * 8);
        }
    };

    int aR128[4], aR7[4];
    const int l4a = (lid >> 4) & 1;
#pragma unroll
    for (int mf = 0; mf < 4; mf++) {
        int r = mw * 64 + mf * 16 + (lid & 7) + 8 * ((lid >> 3) & 1);
        aR128[mf] = r * 128;
        aR7[mf] = r & 7;
    }
    const int t3 = (lid >> 3) & 1;
    const int kkterm = ((lid & 7) + 8 * ((lid >> 4) & 1)) * 256;
    int bOff[4];
#pragma unroll
    for (int p = 0; p < 4; p++)
        bOff[p] = nw * 128 + (((p * 2 + t3) ^ (lid & 7)) << 4);

    float acc[4][8][4];
#pragma unroll
    for (int mf = 0; mf < 4; mf++)
#pragma unroll
        for (int nf = 0; nf < 8; nf++)
#pragma unroll
            for (int e = 0; e < 4; e++) acc[mf][nf][e] = 0.f;

    issueA(0, 0); issueB(0, 0); cp_commit();
    issueA(1, 1); issueB(1, 1); cp_commit();
    asm volatile("cp.async.wait_group 1;");
    __syncthreads();

    for (int t = 0; t < nk; t++) {
        if (t + 2 < nk) {
            issueA(t + 2, (t + 2) % 3);
            issueB(t + 2, (t + 2) % 3);
            cp_commit();
        }

        const uint32_t Ab = smb + (t % 3) * 16384;
        const uint32_t Bb = smb + 49152 + (t % 3) * 16384;

        uint32_t a[2][4][4], b[2][8][2];
        auto ldfr = [&](int kb, int pb) {
#pragma unroll
            for (int mf = 0; mf < 4; mf++)
                ldsm4(a[pb][mf], Ab + aR128[mf] + ((((kb << 1) | l4a) ^ aR7[mf]) << 4));
#pragma unroll
            for (int p = 0; p < 4; p++) {
                uint32_t r[4];
                ldsm4t(r, Bb + kb * 4096 + kkterm + bOff[p]);
                b[pb][2 * p][0] = r[0];     b[pb][2 * p][1] = r[2];
                b[pb][2 * p + 1][0] = r[1]; b[pb][2 * p + 1][1] = r[3];
            }
        };

        ldfr(0, 0);
#pragma unroll
        for (int kb = 0; kb < 4; kb++) {
            if (kb < 3) ldfr(kb + 1, (kb + 1) & 1);
            const int pb = kb & 1;
#pragma unroll
            for (int mf = 0; mf < 4; mf++)
#pragma unroll
                for (int nf = 0; nf < 8; nf++)
                    mma_h(acc[mf][nf], a[pb][mf], b[pb][nf]);
        }

        if (t + 1 < nk) {
            if (t + 2 < nk) asm volatile("cp.async.wait_group 1;");
            else            asm volatile("cp.async.wait_group 0;");
            __syncthreads();
        }
    }

    const int r0 = mw * 64 + (lid >> 2);
    const int c0 = nw * 64 + (lid & 3) * 2;

    if (!FUSE_TAIL) {
        // ---- standard epilogue: bias + relu, pack to half2, store C ----
#pragma unroll
        for (int mf = 0; mf < 4; mf++) {
            const int row = r0 + mf * 16;
#pragma unroll
            for (int nf = 0; nf < 8; nf++) {
                const int col = c0 + nf * 8;
                float2 v0 = make_float2(acc[mf][nf][0], acc[mf][nf][1]);
                float2 v1 = make_float2(acc[mf][nf][2], acc[mf][nf][3]);
                if (bias) {
                    float bx = bias[col], by = bias[col + 1];
                    v0.x += bx; v0.y += by; v1.x += bx; v1.y += by;
                }
                if (relu) {
                    v0.x = fmaxf(v0.x, 0.f); v0.y = fmaxf(v0.y, 0.f);
                    v1.x = fmaxf(v1.x, 0.f); v1.y = fmaxf(v1.y, 0.f);
                }
                *(uint32_t*)(C + (size_t)row * ldb + col) = pack2(v0.x, v0.y);
                *(uint32_t*)(C + (size_t)(row + 8) * ldb + col) = pack2(v1.x, v1.y);
            }
        }
    } else {
        // ---- fused tail epilogue (L1B): part += adj0-weighted column sums ----
        // weights: adj[b, 0, node] for this CTA's 128 node-rows (fp32)
        const float* ar = adjw + (size_t)blockIdx.z * N_ * N_ + blockIdx.y * 128;
        float w0[4], w1[4];
#pragma unroll
        for (int mf = 0; mf < 4; mf++) {
            w0[mf] = ar[r0 + mf * 16];
            w1[mf] = ar[r0 + mf * 16 + 8];
        }
        float psum[16];
#pragma unroll
        for (int j = 0; j < 16; j++) psum[j] = 0.f;
#pragma unroll
        for (int mf = 0; mf < 4; mf++) {
#pragma unroll
            for (int nf = 0; nf < 8; nf++) {
                const int col = c0 + nf * 8;
                float bx = bias[col], by = bias[col + 1];
                float v0x = fmaxf(acc[mf][nf][0] + bx, 0.f);
                float v0y = fmaxf(acc[mf][nf][1] + by, 0.f);
                float v1x = fmaxf(acc[mf][nf][2] + bx, 0.f);
                float v1y = fmaxf(acc[mf][nf][3] + by, 0.f);
                psum[nf * 2 + 0] += w0[mf] * v0x + w1[mf] * v1x;
                psum[nf * 2 + 1] += w0[mf] * v0y + w1[mf] * v1y;
            }
        }
        // reduce over the 8 lanes sharing the same columns (same lid&3)
#pragma unroll
        for (int j = 0; j < 16; j++) {
            psum[j] += __shfl_xor_sync(0xFFFFFFFF, psum[j], 4);
            psum[j] += __shfl_xor_sync(0xFFFFFFFF, psum[j], 8);
            psum[j] += __shfl_xor_sync(0xFFFFFFFF, psum[j], 16);
        }
        // smem reduce across the 2 m-warps; spart[mw][col_local 0..127]
        float* spart = smp;  // mainloop smem reused; 2*128 floats
        __syncthreads();     // all warps done reading smem tiles
        if (lid < 4) {
#pragma unroll
            for (int nf = 0; nf < 8; nf++) {
                int cl = nw * 64 + (lid & 3) * 2 + nf * 8;
                spart[mw * 128 + cl]     = psum[nf * 2 + 0];
                spart[mw * 128 + cl + 1] = psum[nf * 2 + 1];
            }
        }
        __syncthreads();
        if (tid < 128) {
            float tot = spart[tid] + spart[128 + tid];
            part[((size_t)blockIdx.z * 8 + blockIdx.y) * H_ + blockIdx.x * 128 + tid] = tot;
        }
    }
}

// ---------------- prep: all fp32 -> fp16 conversions in ONE kernel ---------
__global__ __launch_bounds__(256)
void cvt_all_kernel(const float4* __restrict__ s0, uint2* __restrict__ d0, int n0,
                    const float4* __restrict__ s1, uint2* __restrict__ d1, int n1,
                    const float4* __restrict__ s2, uint2* __restrict__ d2, int n2,
                    const float4* __restrict__ s3, uint2* __restrict__ d3, int n3)
{
    const int stride = gridDim.x * 256;
    const int t0 = blockIdx.x * 256 + threadIdx.x;
    for (int i = t0; i < n0; i += stride) {
        float4 v = s0[i];
        d0[i] = make_uint2(pack2(v.x, v.y), pack2(v.z, v.w));
    }
    for (int i = t0; i < n1; i += stride) {
        float4 v = s1[i];
        d1[i] = make_uint2(pack2(v.x, v.y), pack2(v.z, v.w));
    }
    for (int i = t0; i < n2; i += stride) {
        float4 v = s2[i];
        d2[i] = make_uint2(pack2(v.x, v.y), pack2(v.z, v.w));
    }
    for (int i = t0; i < n3; i += stride) {
        float4 v = s3[i];
        d3[i] = make_uint2(pack2(v.x, v.y), pack2(v.z, v.w));
    }
}

// ---------------- tail2: reduce part + W2(relu) + Wl head ------------------
__global__ __launch_bounds__(256)
void tail2_kernel(const float* __restrict__ part,
                  const float* __restrict__ W2, const float* __restrict__ b2,
                  const float* __restrict__ Wl, const float* __restrict__ bl,
                  float* __restrict__ out)
{
    const int b = blockIdx.x;
    const int t = threadIdx.x;
    __shared__ float rs[H_];
    __shared__ float ss[H_];

    {
        const float* p = part + b * 8 * H_ + t;
        float a = p[0];
#pragma unroll
        for (int s = 1; s < 8; s++) a += p[s * H_];
        rs[t] = a;
    }
    __syncthreads();

    {
        float a2 = b2[t];
#pragma unroll 8
        for (int k = 0; k < H_; k++)
            a2 = fmaf(rs[k], W2[k * H_ + t], a2);
        ss[t] = fmaxf(a2, 0.f);
    }
    __syncthreads();

    if (t < F_) {
        float a3 = bl[t];
#pragma unroll 8
        for (int k = 0; k < H_; k++)
            a3 = fmaf(ss[k], Wl[k * F_ + t], a3);
        out[b * F_ + t] = a3;
    }
}

// ---------------- launch ----------------
template <int FUSE_TAIL>
static void launch_gemm(const __half* A, const __half* Bm, __half* C,
                        int gridN, int gridM, int batch, int K, int ldb,
                        long sA, long sB, long sC, const float* bias, int relu,
                        const float* adjw, float* part)
{
    const int smem = 98304;
    cudaFuncSetAttribute(gemm_h<FUSE_TAIL>,
                         cudaFuncAttributeMaxDynamicSharedMemorySize, smem);
    gemm_h<FUSE_TAIL><<<dim3(gridN, gridM, batch), 128, smem>>>(
        A, Bm, C, K, K / 64, ldb, sA, sB, sC, bias, relu, adjw, part);
}

extern "C" void kernel_launch(void* const* d_in, const int* in_sizes, int n_in,
                              void* d_out, int out_size)
{
    const float* embs = (const float*)d_in[0];
    const float* adj  = (const float*)d_in[1];
    const float* W0   = (const float*)d_in[2];
    const float* b0   = (const float*)d_in[3];
    const float* W1   = (const float*)d_in[4];
    const float* b1   = (const float*)d_in[5];
    const float* W2   = (const float*)d_in[6];
    const float* b2   = (const float*)d_in[7];
    const float* Wl   = (const float*)d_in[8];
    const float* bl   = (const float*)d_in[9];
    float* out = (float*)d_out;

    __half *adj16, *embs16, *W016, *W116, *T1h, *hid1h, *T2h;
    float* part;
    cudaGetSymbolAddress((void**)&adj16, g_adj16);
    cudaGetSymbolAddress((void**)&embs16, g_embs16);
    cudaGetSymbolAddress((void**)&W016, g_W016);
    cudaGetSymbolAddress((void**)&W116, g_W116);
    cudaGetSymbolAddress((void**)&T1h, g_T1h);
    cudaGetSymbolAddress((void**)&hid1h, g_hid1h);
    cudaGetSymbolAddress((void**)&T2h, g_T2h);
    cudaGetSymbolAddress((void**)&part, g_part);

    // prep: all fp32 -> fp16 in one launch (adj dominates: 268MB read)
    cvt_all_kernel<<<2048, 256>>>(
        (const float4*)adj, (uint2*)adj16, (int)((size_t)B_ * N_ * N_ / 4),
        (const float4*)embs, (uint2*)embs16, B_ * N_ * F_ / 4,
        (const float4*)W0, (uint2*)W016, F_ * H_ / 4,
        (const float4*)W1, (uint2*)W116, H_ * H_ / 4);

    // L0A: T1 = adj @ embs            per graph [1024x1024]@[1024x128]
    launch_gemm<0>(adj16, embs16, T1h, 1, 8, B_, N_, F_,
                   (long)N_ * N_, (long)N_ * F_, (long)N_ * F_, nullptr, 0,
                   nullptr, nullptr);
    // L0B: hid1 = relu(T1 @ W0 + b0)  [65536x128]@[128x256]
    launch_gemm<0>(T1h, W016, hid1h, 2, 512, 1, F_, H_, 0, 0, 0, b0, 1,
                   nullptr, nullptr);
    // L1A: T2 = hid1 @ W1             [65536x256]@[256x256]
    launch_gemm<0>(hid1h, W116, T2h, 2, 512, 1, H_, H_, 0, 0, 0, nullptr, 0,
                   nullptr, nullptr);
    // L1B fused with tail1: part[b][yt][col] = sum over CTA rows of
    //   adj[b,0,row] * relu((adj@T2)[row,col] + b1[col]);  hid2 never stored.
    launch_gemm<1>(adj16, T2h, nullptr, 2, 8, B_, N_, H_,
                   (long)N_ * N_, (long)N_ * H_, 0, b1, 1, adj, part);
    // tail2: reduce 8 ytiles + W2(relu) + Wl head
    tail2_kernel<<<B_, 256>>>(part, W2, b2, Wl, bl, out);
}